// round 10
// baseline (speedup 1.0000x reference)
#include <cuda_runtime.h>
#include <cuda_bf16.h>
#include <cstdint>

#define SS   512
#define G4   512
#define HH   128
#define DD   128
#define VSZ  64000
#define BC   8
#define NCTA 128
#define NOPS 16
#define PP   10   // preact smem pitch (floats) — even for STS.64, conflict-light

typedef unsigned int u32;
typedef unsigned long long u64;

// ---------------- device globals ----------------
__device__ __align__(16) __nv_bfloat16 g_Wih_bf[G4 * DD];  // row-major [gate][k]
__device__ __align__(16) __nv_bfloat16 g_Whh_bf[G4 * HH];
__device__ float g_bias[G4];
// xg[token][j*4 + type] bf16: x-path precomputed with bias (i,f,g,o per j)
__device__ __align__(16) __nv_bfloat16 g_xg[(size_t)VSZ * G4];  // 64 MB

// ---------------- helpers ----------------
__device__ __forceinline__ u32 smem_u32(const void* p) {
    u32 a;
    asm("{ .reg .u64 t; cvta.to.shared.u64 t, %1; cvt.u32.u64 %0, t; }" : "=r"(a) : "l"(p));
    return a;
}
__device__ __forceinline__ void mma16816(float* d, const u32* a, const u32* b) {
    asm volatile(
        "mma.sync.aligned.m16n8k16.row.col.f32.bf16.bf16.f32 "
        "{%0,%1,%2,%3},{%4,%5,%6,%7},{%8,%9},{%0,%1,%2,%3};"
        : "+f"(d[0]), "+f"(d[1]), "+f"(d[2]), "+f"(d[3])
        : "r"(a[0]), "r"(a[1]), "r"(a[2]), "r"(a[3]), "r"(b[0]), "r"(b[1]));
}
__device__ __forceinline__ void ldsm_x2t(u32* r, u32 addr) {
    asm volatile("ldmatrix.sync.aligned.m8n8.x2.trans.shared.b16 {%0,%1},[%2];"
                 : "=r"(r[0]), "=r"(r[1]) : "r"(addr));
}
__device__ __forceinline__ float ex2_ap(float x) {
    float y; asm("ex2.approx.f32 %0, %1;" : "=f"(y) : "f"(x)); return y;
}
__device__ __forceinline__ float rcp_ap(float x) {
    float y; asm("rcp.approx.f32 %0, %1;" : "=f"(y) : "f"(x)); return y;
}
__device__ __forceinline__ float tanh_ap(float x) {
    float y; asm("tanh.approx.f32 %0, %1;" : "=f"(y) : "f"(x)); return y;
}
__device__ __forceinline__ float sig_ap(float x) {
    return fmaf(tanh_ap(x * 0.5f), 0.5f, 0.5f);
}
// accurate tanh (protects the c -> h path)
__device__ __forceinline__ float tanh_acc(float x) {
    return 1.f - 2.f * rcp_ap(1.f + ex2_ap(2.885390081777927f * x));
}
__device__ __forceinline__ float bf_lo(u32 p) { return __uint_as_float(p << 16); }
__device__ __forceinline__ float bf_hi(u32 p) { return __uint_as_float(p & 0xFFFF0000u); }

// ---------------- setup ----------------
__global__ void setup_kernel(const float* __restrict__ Wih, const float* __restrict__ Whh,
                             const float* __restrict__ bih, const float* __restrict__ bhh) {
    int idx = blockIdx.x * blockDim.x + threadIdx.x;
    int which = idx >> 16;
    int e = idx & 65535;
    if (which == 0)
        g_Wih_bf[e] = __float2bfloat16(Wih[e]);
    else
        g_Whh_bf[e] = __float2bfloat16(Whh[e]);
    if (idx < G4) g_bias[idx] = bih[idx] + bhh[idx];
}

// ---------------- Phase A: xg = W_ih @ relu(emb) + bias, all tokens ----------------
#define XPITCH 272
__global__ void __launch_bounds__(256, 1)
phaseA_kernel(const float* __restrict__ emb) {
    __shared__ __align__(16) unsigned char sX[128 * XPITCH];
    const int tid = threadIdx.x;
    const int w = tid >> 5, lane = tid & 31;
    const int tokbase = blockIdx.x * 128;

    {
        int r = tid >> 1, half = tid & 1;
        const float* er = emb + (size_t)(tokbase + r) * DD + half * 64;
#pragma unroll 4
        for (int cc = 0; cc < 64; cc += 4) {
            float4 f = *(const float4*)(er + cc);
            int d0 = half * 64 + cc;
            *(__nv_bfloat16*)(sX + (d0 + 0) * XPITCH + r * 2) = __float2bfloat16(fmaxf(f.x, 0.f));
            *(__nv_bfloat16*)(sX + (d0 + 1) * XPITCH + r * 2) = __float2bfloat16(fmaxf(f.y, 0.f));
            *(__nv_bfloat16*)(sX + (d0 + 2) * XPITCH + r * 2) = __float2bfloat16(fmaxf(f.z, 0.f));
            *(__nv_bfloat16*)(sX + (d0 + 3) * XPITCH + r * 2) = __float2bfloat16(fmaxf(f.w, 0.f));
        }
    }

    u32 a[4][8][4];
#pragma unroll
    for (int mt = 0; mt < 4; mt++) {
        int g1 = mt * 128 + w * 16 + (lane >> 2);
        int kc = (lane & 3) * 2;
#pragma unroll
        for (int kt = 0; kt < 8; kt++) {
            const __nv_bfloat16* Wp = g_Wih_bf + g1 * DD + kt * 16 + kc;
            a[mt][kt][0] = *(const u32*)(Wp);
            a[mt][kt][1] = *(const u32*)(Wp + 8 * DD);
            a[mt][kt][2] = *(const u32*)(Wp + 8);
            a[mt][kt][3] = *(const u32*)(Wp + 8 * DD + 8);
        }
    }
    float bs[4][2];
#pragma unroll
    for (int mt = 0; mt < 4; mt++) {
        bs[mt][0] = g_bias[mt * 128 + w * 16 + (lane >> 2)];
        bs[mt][1] = g_bias[mt * 128 + w * 16 + (lane >> 2) + 8];
    }
    __syncthreads();

    u32 xb = smem_u32(sX);
    const int jb = w * 16 + (lane >> 2);
    const int n0 = (lane & 3) * 2;

    for (int nt = 0; nt < 16; nt++) {
        u32 bf[8][2];
#pragma unroll
        for (int kt = 0; kt < 8; kt++)
            ldsm_x2t(bf[kt], xb + (kt * 16 + (lane & 15)) * XPITCH + nt * 16);
        float acc[4][4];
#pragma unroll
        for (int mt = 0; mt < 4; mt++) {
            acc[mt][0] = acc[mt][1] = acc[mt][2] = acc[mt][3] = 0.f;
#pragma unroll
            for (int kt = 0; kt < 8; kt++) mma16816(acc[mt], a[mt][kt], bf[kt]);
        }
#pragma unroll
        for (int e = 0; e < 4; e++) {
            int j = jb + (e >> 1) * 8;
            int tok = tokbase + nt * 8 + n0 + (e & 1);
            __nv_bfloat162 p0 = __floats2bfloat162_rn(acc[0][e] + bs[0][e >> 1],
                                                      acc[1][e] + bs[1][e >> 1]);
            __nv_bfloat162 p1 = __floats2bfloat162_rn(acc[2][e] + bs[2][e >> 1],
                                                      acc[3][e] + bs[3][e >> 1]);
            uint2 v = make_uint2(*(u32*)&p0, *(u32*)&p1);
            *(uint2*)(g_xg + (size_t)tok * G4 + j * 4) = v;
        }
    }
}

// ---------------- recurrent kernel: 512 threads, gate exchange via smem ----------------
__global__ void __launch_bounds__(512, 1)
lstm_rec(const int* __restrict__ tokens, const int* __restrict__ lengths,
         const float* __restrict__ onehot, const float* __restrict__ h0,
         const float* __restrict__ c0, const float* __restrict__ linW,
         const float* __restrict__ linb, float* __restrict__ out) {
    __shared__ __align__(16) unsigned char hb[2][HH * 16];  // double-buffered h tile [k][s] bf16
    __shared__ __align__(16) float sp[G4 * PP];             // gate preacts [g][s] pitch PP
    __shared__ int stok[BC * SS];
    __shared__ float shl[BC * HH];

    const int tid = threadIdx.x;
    const int w = tid >> 5, lane = tid & 31;
    const int base_s = blockIdx.x * BC;

    for (int i = tid; i < BC * SS; i += 512) {
        int s = i >> 9, t = i & 511;
        stok[s * SS + t] = tokens[(size_t)(base_s + s) * SS + t];
    }
    for (int i = tid; i < HH * BC; i += 512) {
        int j = i >> 3, s = i & 7;
        *(__nv_bfloat16*)(hb[0] + j * 16 + s * 2) = __float2bfloat16(h0[j]);
    }

    // MMA phase state: warp w owns m-tiles {2w, 2w+1}; A-frags register-resident
    u32 a[2][8][4];
#pragma unroll
    for (int mt = 0; mt < 2; mt++) {
        int g1 = (2 * w + mt) * 16 + (lane >> 2);
        int kc = (lane & 3) * 2;
#pragma unroll
        for (int kt = 0; kt < 8; kt++) {
            const __nv_bfloat16* Wp = g_Whh_bf + g1 * HH + kt * 16 + kc;
            a[mt][kt][0] = *(const u32*)(Wp);
            a[mt][kt][1] = *(const u32*)(Wp + 8 * HH);
            a[mt][kt][2] = *(const u32*)(Wp + 8);
            a[mt][kt][3] = *(const u32*)(Wp + 8 * HH + 8);
        }
    }
    const int gr = (lane >> 2);        // row within tile
    const int sn0 = (lane & 3) * 2;    // sample col for d0/d1

    // update phase state: thread owns cells (j, s0) and (j, s0+1)
    const int j = tid >> 2;
    const int s0 = (tid & 3) * 2;
    u32 hbase0 = smem_u32(hb[0]);
    u32 hbase1 = smem_u32(hb[1]);

    float c[2], hl[2];
    int len0 = lengths[base_s + s0];
    int len1 = lengths[base_s + s0 + 1];
    c[0] = c[1] = c0[j];
    hl[0] = hl[1] = 0.f;

    // 2-deep xg prefetch (u64 = 4 bf16 gate types for (tok, j))
    u64 x0[2], x1[2];
#pragma unroll
    for (int q = 0; q < 2; q++) {
        x0[q] = *(const u64*)(g_xg + (size_t)stok[(s0 + q) * SS + 0] * G4 + j * 4);
        x1[q] = *(const u64*)(g_xg + (size_t)stok[(s0 + q) * SS + 1] * G4 + j * 4);
    }
    __syncthreads();

    int p = 0;
    for (int t = 0; t < SS; t++) {
        // prefetch xg for t+2
        u64 x2[2] = {0, 0};
        if (t + 2 < SS) {
#pragma unroll
            for (int q = 0; q < 2; q++)
                x2[q] = *(const u64*)(g_xg + (size_t)stok[(s0 + q) * SS + t + 2] * G4 + j * 4);
        }

        // ---- MMA phase ----
        u32 hrd = p ? hbase1 : hbase0;
        u32 bf[8][2];
#pragma unroll
        for (int kt = 0; kt < 8; kt++)
            ldsm_x2t(bf[kt], hrd + (kt * 16 + (lane & 15)) * 16);

        float acc[2][4];
#pragma unroll
        for (int mt = 0; mt < 2; mt++) {
            acc[mt][0] = acc[mt][1] = acc[mt][2] = acc[mt][3] = 0.f;
#pragma unroll
            for (int kt = 0; kt < 8; kt++) mma16816(acc[mt], a[mt][kt], bf[kt]);
        }
        // write preacts: rows (tile*16+gr) and (+8), sample pairs (sn0, sn0+1)
#pragma unroll
        for (int mt = 0; mt < 2; mt++) {
            int g0 = (2 * w + mt) * 16 + gr;
            *(float2*)(sp + g0 * PP + sn0) = make_float2(acc[mt][0], acc[mt][1]);
            *(float2*)(sp + (g0 + 8) * PP + sn0) = make_float2(acc[mt][2], acc[mt][3]);
        }
        __syncthreads();  // preacts visible

        // ---- update phase: cells (j, s0) and (j, s0+1) ----
        float2 vi = *(const float2*)(sp + (0 * HH + j) * PP + s0);
        float2 vf = *(const float2*)(sp + (1 * HH + j) * PP + s0);
        float2 vg = *(const float2*)(sp + (2 * HH + j) * PP + s0);
        float2 vo = *(const float2*)(sp + (3 * HH + j) * PP + s0);
        unsigned char* hwr = hb[p ^ 1];
#pragma unroll
        for (int q = 0; q < 2; q++) {
            u32 lo = (u32)x0[q], hi = (u32)(x0[q] >> 32);
            float pi = (q ? vi.y : vi.x) + bf_lo(lo);
            float pf = (q ? vf.y : vf.x) + bf_hi(lo);
            float pg = (q ? vg.y : vg.x) + bf_lo(hi);
            float po = (q ? vo.y : vo.x) + bf_hi(hi);
            float iv = sig_ap(pi), fv = sig_ap(pf), ov = sig_ap(po);
            float gv = tanh_ap(pg);
            c[q] = fmaf(fv, c[q], iv * gv);
            float h = ov * tanh_acc(c[q]);
            if (t == (q ? len1 : len0) - 1) hl[q] = fmaxf(h, 0.f);
            *(__nv_bfloat16*)(hwr + j * 16 + (s0 + q) * 2) = __float2bfloat16(h);
        }
        __syncthreads();  // h(t+1) complete before next ldmatrix
#pragma unroll
        for (int q = 0; q < 2; q++) { x0[q] = x1[q]; x1[q] = x2[q]; }
        p ^= 1;
    }

    shl[s0 * HH + j] = hl[0];
    shl[(s0 + 1) * HH + j] = hl[1];
    __syncthreads();
    if (tid < BC * 2) {
        int s = tid >> 1, m = tid & 1;
        const float* wrow = linW + m * (HH + NOPS);
        float acc = linb[m];
#pragma unroll 8
        for (int jj = 0; jj < HH; jj++) acc = fmaf(shl[s * HH + jj], wrow[jj], acc);
#pragma unroll
        for (int pp2 = 0; pp2 < NOPS; pp2++)
            acc = fmaf(onehot[(base_s + s) * NOPS + pp2], wrow[HH + pp2], acc);
        out[(base_s + s) * 2 + m] = acc;
    }
}

// ---------------- launch ----------------
extern "C" void kernel_launch(void* const* d_in, const int* in_sizes, int n_in,
                              void* d_out, int out_size) {
    const int* tokens = (const int*)d_in[0];
    const int* lengths = (const int*)d_in[1];
    const float* onehot = (const float*)d_in[2];
    const float* emb = (const float*)d_in[3];
    const float* Wih = (const float*)d_in[4];
    const float* Whh = (const float*)d_in[5];
    const float* bih = (const float*)d_in[6];
    const float* bhh = (const float*)d_in[7];
    const float* h0 = (const float*)d_in[8];
    const float* c0 = (const float*)d_in[9];
    const float* linW = (const float*)d_in[10];
    const float* linb = (const float*)d_in[11];
    float* out = (float*)d_out;

    setup_kernel<<<512, 256>>>(Wih, Whh, bih, bhh);
    phaseA_kernel<<<VSZ / 128, 256>>>(emb);
    lstm_rec<<<NCTA, 512>>>(tokens, lengths, onehot, h0, c0, linW, linb, out);
}

// round 13
// speedup vs baseline: 1.2771x; 1.2771x over previous
#include <cuda_runtime.h>
#include <cuda_bf16.h>
#include <cstdint>

#define SS   512
#define G4   512
#define HH   128
#define DD   128
#define VSZ  64000
#define BC   8
#define NCTA 128
#define NOPS 16

typedef unsigned int u32;
typedef unsigned long long u64;

// ---------------- device globals ----------------
__device__ __align__(16) __nv_bfloat16 g_Wih_bf[G4 * DD];  // row-major [gate][k]
__device__ __align__(16) __nv_bfloat16 g_Whh_bf[G4 * HH];
__device__ float g_bias[G4];
// xg[token][j*4 + type] bf16: x-path precomputed with bias (i,f,g,o per j)
__device__ __align__(16) __nv_bfloat16 g_xg[(size_t)VSZ * G4];  // 64 MB

// ---------------- helpers ----------------
__device__ __forceinline__ u32 smem_u32(const void* p) {
    u32 a;
    asm("{ .reg .u64 t; cvta.to.shared.u64 t, %1; cvt.u32.u64 %0, t; }" : "=r"(a) : "l"(p));
    return a;
}
__device__ __forceinline__ void mma16816(float* d, const u32* a, const u32* b) {
    asm volatile(
        "mma.sync.aligned.m16n8k16.row.col.f32.bf16.bf16.f32 "
        "{%0,%1,%2,%3},{%4,%5,%6,%7},{%8,%9},{%0,%1,%2,%3};"
        : "+f"(d[0]), "+f"(d[1]), "+f"(d[2]), "+f"(d[3])
        : "r"(a[0]), "r"(a[1]), "r"(a[2]), "r"(a[3]), "r"(b[0]), "r"(b[1]));
}
__device__ __forceinline__ void ldsm_x2t(u32* r, u32 addr) {
    asm volatile("ldmatrix.sync.aligned.m8n8.x2.trans.shared.b16 {%0,%1},[%2];"
                 : "=r"(r[0]), "=r"(r[1]) : "r"(addr));
}
__device__ __forceinline__ float ex2_ap(float x) {
    float y; asm("ex2.approx.f32 %0, %1;" : "=f"(y) : "f"(x)); return y;
}
__device__ __forceinline__ float rcp_ap(float x) {
    float y; asm("rcp.approx.f32 %0, %1;" : "=f"(y) : "f"(x)); return y;
}
__device__ __forceinline__ float tanh_ap(float x) {
    float y; asm("tanh.approx.f32 %0, %1;" : "=f"(y) : "f"(x)); return y;
}
__device__ __forceinline__ float sig_ap(float x) {
    return fmaf(tanh_ap(x * 0.5f), 0.5f, 0.5f);
}
// accurate tanh (output-path h_last capture only)
__device__ __forceinline__ float tanh_acc(float x) {
    return 1.f - 2.f * rcp_ap(1.f + ex2_ap(2.885390081777927f * x));
}
__device__ __forceinline__ float bf_lo(u32 p) { return __uint_as_float(p << 16); }
__device__ __forceinline__ float bf_hi(u32 p) { return __uint_as_float(p & 0xFFFF0000u); }

// ---------------- setup ----------------
__global__ void setup_kernel(const float* __restrict__ Wih, const float* __restrict__ Whh,
                             const float* __restrict__ bih, const float* __restrict__ bhh) {
    int idx = blockIdx.x * blockDim.x + threadIdx.x;
    int which = idx >> 16;
    int e = idx & 65535;
    if (which == 0)
        g_Wih_bf[e] = __float2bfloat16(Wih[e]);
    else
        g_Whh_bf[e] = __float2bfloat16(Whh[e]);
    if (idx < G4) g_bias[idx] = bih[idx] + bhh[idx];
}

// ---------------- Phase A: xg = W_ih @ relu(emb) + bias, all tokens ----------------
#define XPITCH 272
__global__ void __launch_bounds__(256, 1)
phaseA_kernel(const float* __restrict__ emb) {
    __shared__ __align__(16) unsigned char sX[128 * XPITCH];
    const int tid = threadIdx.x;
    const int w = tid >> 5, lane = tid & 31;
    const int tokbase = blockIdx.x * 128;

    {
        int r = tid >> 1, half = tid & 1;
        const float* er = emb + (size_t)(tokbase + r) * DD + half * 64;
#pragma unroll 4
        for (int cc = 0; cc < 64; cc += 4) {
            float4 f = *(const float4*)(er + cc);
            int d0 = half * 64 + cc;
            *(__nv_bfloat16*)(sX + (d0 + 0) * XPITCH + r * 2) = __float2bfloat16(fmaxf(f.x, 0.f));
            *(__nv_bfloat16*)(sX + (d0 + 1) * XPITCH + r * 2) = __float2bfloat16(fmaxf(f.y, 0.f));
            *(__nv_bfloat16*)(sX + (d0 + 2) * XPITCH + r * 2) = __float2bfloat16(fmaxf(f.z, 0.f));
            *(__nv_bfloat16*)(sX + (d0 + 3) * XPITCH + r * 2) = __float2bfloat16(fmaxf(f.w, 0.f));
        }
    }

    u32 a[4][8][4];
#pragma unroll
    for (int mt = 0; mt < 4; mt++) {
        int g1 = mt * 128 + w * 16 + (lane >> 2);
        int kc = (lane & 3) * 2;
#pragma unroll
        for (int kt = 0; kt < 8; kt++) {
            const __nv_bfloat16* Wp = g_Wih_bf + g1 * DD + kt * 16 + kc;
            a[mt][kt][0] = *(const u32*)(Wp);
            a[mt][kt][1] = *(const u32*)(Wp + 8 * DD);
            a[mt][kt][2] = *(const u32*)(Wp + 8);
            a[mt][kt][3] = *(const u32*)(Wp + 8 * DD + 8);
        }
    }
    float bs[4][2];
#pragma unroll
    for (int mt = 0; mt < 4; mt++) {
        bs[mt][0] = g_bias[mt * 128 + w * 16 + (lane >> 2)];
        bs[mt][1] = g_bias[mt * 128 + w * 16 + (lane >> 2) + 8];
    }
    __syncthreads();

    u32 xb = smem_u32(sX);
    const int jb = w * 16 + (lane >> 2);
    const int n0 = (lane & 3) * 2;

    for (int nt = 0; nt < 16; nt++) {
        u32 bf[8][2];
#pragma unroll
        for (int kt = 0; kt < 8; kt++)
            ldsm_x2t(bf[kt], xb + (kt * 16 + (lane & 15)) * XPITCH + nt * 16);
        float acc[4][4];
#pragma unroll
        for (int mt = 0; mt < 4; mt++) {
            acc[mt][0] = acc[mt][1] = acc[mt][2] = acc[mt][3] = 0.f;
#pragma unroll
            for (int kt = 0; kt < 8; kt++) mma16816(acc[mt], a[mt][kt], bf[kt]);
        }
#pragma unroll
        for (int e = 0; e < 4; e++) {
            int j = jb + (e >> 1) * 8;
            int tok = tokbase + nt * 8 + n0 + (e & 1);
            __nv_bfloat162 p0 = __floats2bfloat162_rn(acc[0][e] + bs[0][e >> 1],
                                                      acc[1][e] + bs[1][e >> 1]);
            __nv_bfloat162 p1 = __floats2bfloat162_rn(acc[2][e] + bs[2][e >> 1],
                                                      acc[3][e] + bs[3][e >> 1]);
            uint2 v = make_uint2(*(u32*)&p0, *(u32*)&p1);
            *(uint2*)(g_xg + (size_t)tok * G4 + j * 4) = v;
        }
    }
}

// ---------------- recurrent kernel (R9 structure + split-K + fast recurrent tanh) ----------------
__global__ void __launch_bounds__(256, 1)
lstm_rec(const int* __restrict__ tokens, const int* __restrict__ lengths,
         const float* __restrict__ onehot, const float* __restrict__ h0,
         const float* __restrict__ c0, const float* __restrict__ linW,
         const float* __restrict__ linb, float* __restrict__ out) {
    __shared__ __align__(16) unsigned char hb[2][HH * 16];  // double-buffered h tile [k][s] bf16
    __shared__ int stok[BC * SS];
    __shared__ float shl[BC * HH];

    const int tid = threadIdx.x;
    const int w = tid >> 5, lane = tid & 31;
    const int base_s = blockIdx.x * BC;

    for (int i = tid; i < BC * SS; i += 256) {
        int s = i >> 9, t = i & 511;
        stok[s * SS + t] = tokens[(size_t)(base_s + s) * SS + t];
    }
    for (int i = tid; i < HH * BC; i += 256) {
        int j = i >> 3, s = i & 7;
        *(__nv_bfloat16*)(hb[0] + j * 16 + s * 2) = __float2bfloat16(h0[j]);
    }

    // A fragments (W_hh) register-resident for all 512 steps
    u32 a[4][8][4];
#pragma unroll
    for (int mt = 0; mt < 4; mt++) {
        int g1 = mt * 128 + w * 16 + (lane >> 2);
        int kc = (lane & 3) * 2;
#pragma unroll
        for (int kt = 0; kt < 8; kt++) {
            const __nv_bfloat16* Wp = g_Whh_bf + g1 * HH + kt * 16 + kc;
            a[mt][kt][0] = *(const u32*)(Wp);
            a[mt][kt][1] = *(const u32*)(Wp + 8 * HH);
            a[mt][kt][2] = *(const u32*)(Wp + 8);
            a[mt][kt][3] = *(const u32*)(Wp + 8 * HH + 8);
        }
    }

    const int jb = w * 16 + (lane >> 2);
    const int s0 = (lane & 3) * 2;
    u32 hbase0 = smem_u32(hb[0]);
    u32 hbase1 = smem_u32(hb[1]);

    float c[4], hl[4];
    int len_[2];
    len_[0] = lengths[base_s + s0];
    len_[1] = lengths[base_s + s0 + 1];
#pragma unroll
    for (int e = 0; e < 4; e++) {
        c[e] = c0[jb + (e >> 1) * 8];
        hl[e] = 0.f;
    }

    // 2-deep xg prefetch queue (bf16x4 per cell = u64)
    u64 x0[4], x1[4];
#pragma unroll
    for (int e = 0; e < 4; e++) {
        int j = jb + (e >> 1) * 8;
        int tokA = stok[(s0 + (e & 1)) * SS + 0];
        x0[e] = *(const u64*)(g_xg + (size_t)tokA * G4 + j * 4);
        int tokB = stok[(s0 + (e & 1)) * SS + 1];
        x1[e] = *(const u64*)(g_xg + (size_t)tokB * G4 + j * 4);
    }
    __syncthreads();

    int p = 0;
    for (int t = 0; t < SS; t++) {
        // prefetch xg for t+2 (covers DRAM latency across two steps)
        u64 x2[4] = {0, 0, 0, 0};
        if (t + 2 < SS) {
#pragma unroll
            for (int e = 0; e < 4; e++) {
                int j = jb + (e >> 1) * 8;
                int tok = stok[(s0 + (e & 1)) * SS + t + 2];
                x2[e] = *(const u64*)(g_xg + (size_t)tok * G4 + j * 4);
            }
        }

        u32 hrd = p ? hbase1 : hbase0;
        unsigned char* hwr = hb[p ^ 1];

        // B fragments via proven 8x ldmatrix.x2 (lanes 0-15 supply addresses)
        u32 bf[8][2];
#pragma unroll
        for (int kt = 0; kt < 8; kt++)
            ldsm_x2t(bf[kt], hrd + (kt * 16 + (lane & 15)) * 16);

        // split-K: two independent 4-deep HMMA chains per m-tile
        float acc[4][4], ac2[4][4];
#pragma unroll
        for (int mt = 0; mt < 4; mt++) {
            acc[mt][0] = acc[mt][1] = acc[mt][2] = acc[mt][3] = 0.f;
            ac2[mt][0] = ac2[mt][1] = ac2[mt][2] = ac2[mt][3] = 0.f;
#pragma unroll
            for (int kt = 0; kt < 4; kt++) mma16816(acc[mt], a[mt][kt], bf[kt]);
#pragma unroll
            for (int kt = 4; kt < 8; kt++) mma16816(ac2[mt], a[mt][kt], bf[kt]);
        }

#pragma unroll
        for (int e = 0; e < 4; e++) {
            int j = jb + (e >> 1) * 8;
            int s = s0 + (e & 1);
            u32 lo = (u32)x0[e], hi = (u32)(x0[e] >> 32);
            float pi = (acc[0][e] + ac2[0][e]) + bf_lo(lo);
            float pf = (acc[1][e] + ac2[1][e]) + bf_hi(lo);
            float pg = (acc[2][e] + ac2[2][e]) + bf_lo(hi);
            float po = (acc[3][e] + ac2[3][e]) + bf_hi(hi);
            float iv = sig_ap(pi), fv = sig_ap(pf), ov = sig_ap(po);
            float gv = tanh_ap(pg);
            c[e] = fmaf(fv, c[e], iv * gv);
            float h = ov * tanh_ap(c[e]);  // fast path feeds recurrence
            if (t == len_[e & 1] - 1) hl[e] = fmaxf(ov * tanh_acc(c[e]), 0.f);  // accurate capture
            *(__nv_bfloat16*)(hwr + j * 16 + s * 2) = __float2bfloat16(h);
        }
        __syncthreads();  // h(t+1) tile visible; releases read buffer
#pragma unroll
        for (int e = 0; e < 4; e++) { x0[e] = x1[e]; x1[e] = x2[e]; }
        p ^= 1;
    }

#pragma unroll
    for (int e = 0; e < 4; e++)
        shl[(s0 + (e & 1)) * HH + jb + (e >> 1) * 8] = hl[e];
    __syncthreads();
    if (tid < BC * 2) {
        int s = tid >> 1, m = tid & 1;
        const float* wrow = linW + m * (HH + NOPS);
        float acc = linb[m];
#pragma unroll 8
        for (int jj = 0; jj < HH; jj++) acc = fmaf(shl[s * HH + jj], wrow[jj], acc);
#pragma unroll
        for (int pp = 0; pp < NOPS; pp++)
            acc = fmaf(onehot[(base_s + s) * NOPS + pp], wrow[HH + pp], acc);
        out[(base_s + s) * 2 + m] = acc;
    }
}

// ---------------- launch ----------------
extern "C" void kernel_launch(void* const* d_in, const int* in_sizes, int n_in,
                              void* d_out, int out_size) {
    const int* tokens = (const int*)d_in[0];
    const int* lengths = (const int*)d_in[1];
    const float* onehot = (const float*)d_in[2];
    const float* emb = (const float*)d_in[3];
    const float* Wih = (const float*)d_in[4];
    const float* Whh = (const float*)d_in[5];
    const float* bih = (const float*)d_in[6];
    const float* bhh = (const float*)d_in[7];
    const float* h0 = (const float*)d_in[8];
    const float* c0 = (const float*)d_in[9];
    const float* linW = (const float*)d_in[10];
    const float* linb = (const float*)d_in[11];
    float* out = (float*)d_out;

    setup_kernel<<<512, 256>>>(Wih, Whh, bih, bhh);
    phaseA_kernel<<<VSZ / 128, 256>>>(emb);
    lstm_rec<<<NCTA, 256>>>(tokens, lengths, onehot, h0, c0, linW, linb, out);
}

// round 15
// speedup vs baseline: 1.3749x; 1.0766x over previous
#include <cuda_runtime.h>
#include <cuda_bf16.h>
#include <cstdint>

#define SS   512
#define G4   512
#define HH   128
#define DD   128
#define VSZ  64000
#define BC   8
#define NCTA 128
#define NOPS 16

typedef unsigned int u32;
typedef unsigned long long u64;

// ---------------- device globals ----------------
__device__ __align__(16) __nv_bfloat16 g_Wih_bf[G4 * DD];  // row-major [gate][k]
__device__ __align__(16) __nv_bfloat16 g_Whh_bf[G4 * HH];
__device__ float g_bias[G4];
// xg[token][j*4 + type] bf16: x-path precomputed with bias (i,f,g,o per j)
__device__ __align__(16) __nv_bfloat16 g_xg[(size_t)VSZ * G4];  // 64 MB

// ---------------- helpers ----------------
__device__ __forceinline__ u32 smem_u32(const void* p) {
    u32 a;
    asm("{ .reg .u64 t; cvta.to.shared.u64 t, %1; cvt.u32.u64 %0, t; }" : "=r"(a) : "l"(p));
    return a;
}
__device__ __forceinline__ void mma16816(float* d, const u32* a, const u32* b) {
    asm volatile(
        "mma.sync.aligned.m16n8k16.row.col.f32.bf16.bf16.f32 "
        "{%0,%1,%2,%3},{%4,%5,%6,%7},{%8,%9},{%0,%1,%2,%3};"
        : "+f"(d[0]), "+f"(d[1]), "+f"(d[2]), "+f"(d[3])
        : "r"(a[0]), "r"(a[1]), "r"(a[2]), "r"(a[3]), "r"(b[0]), "r"(b[1]));
}
__device__ __forceinline__ void ldsm_x2t(u32* r, u32 addr) {
    asm volatile("ldmatrix.sync.aligned.m8n8.x2.trans.shared.b16 {%0,%1},[%2];"
                 : "=r"(r[0]), "=r"(r[1]) : "r"(addr));
}
__device__ __forceinline__ float ex2_ap(float x) {
    float y; asm("ex2.approx.f32 %0, %1;" : "=f"(y) : "f"(x)); return y;
}
__device__ __forceinline__ float rcp_ap(float x) {
    float y; asm("rcp.approx.f32 %0, %1;" : "=f"(y) : "f"(x)); return y;
}
__device__ __forceinline__ float tanh_ap(float x) {
    float y; asm("tanh.approx.f32 %0, %1;" : "=f"(y) : "f"(x)); return y;
}
__device__ __forceinline__ float sig_ap(float x) {
    return fmaf(tanh_ap(x * 0.5f), 0.5f, 0.5f);
}
// accurate tanh (output-path h_last capture only)
__device__ __forceinline__ float tanh_acc(float x) {
    return 1.f - 2.f * rcp_ap(1.f + ex2_ap(2.885390081777927f * x));
}
__device__ __forceinline__ float bf_lo(u32 p) { return __uint_as_float(p << 16); }
__device__ __forceinline__ float bf_hi(u32 p) { return __uint_as_float(p & 0xFFFF0000u); }

// ---------------- setup ----------------
__global__ void setup_kernel(const float* __restrict__ Wih, const float* __restrict__ Whh,
                             const float* __restrict__ bih, const float* __restrict__ bhh) {
    int idx = blockIdx.x * blockDim.x + threadIdx.x;
    int which = idx >> 16;
    int e = idx & 65535;
    if (which == 0)
        g_Wih_bf[e] = __float2bfloat16(Wih[e]);
    else
        g_Whh_bf[e] = __float2bfloat16(Whh[e]);
    if (idx < G4) g_bias[idx] = bih[idx] + bhh[idx];
}

// ---------------- Phase A: xg = W_ih @ relu(emb) + bias, all tokens ----------------
#define XPITCH 272
__global__ void __launch_bounds__(256, 1)
phaseA_kernel(const float* __restrict__ emb) {
    __shared__ __align__(16) unsigned char sX[128 * XPITCH];
    const int tid = threadIdx.x;
    const int w = tid >> 5, lane = tid & 31;
    const int tokbase = blockIdx.x * 128;

    {
        int r = tid >> 1, half = tid & 1;
        const float* er = emb + (size_t)(tokbase + r) * DD + half * 64;
#pragma unroll 4
        for (int cc = 0; cc < 64; cc += 4) {
            float4 f = *(const float4*)(er + cc);
            int d0 = half * 64 + cc;
            *(__nv_bfloat16*)(sX + (d0 + 0) * XPITCH + r * 2) = __float2bfloat16(fmaxf(f.x, 0.f));
            *(__nv_bfloat16*)(sX + (d0 + 1) * XPITCH + r * 2) = __float2bfloat16(fmaxf(f.y, 0.f));
            *(__nv_bfloat16*)(sX + (d0 + 2) * XPITCH + r * 2) = __float2bfloat16(fmaxf(f.z, 0.f));
            *(__nv_bfloat16*)(sX + (d0 + 3) * XPITCH + r * 2) = __float2bfloat16(fmaxf(f.w, 0.f));
        }
    }

    u32 a[4][8][4];
#pragma unroll
    for (int mt = 0; mt < 4; mt++) {
        int g1 = mt * 128 + w * 16 + (lane >> 2);
        int kc = (lane & 3) * 2;
#pragma unroll
        for (int kt = 0; kt < 8; kt++) {
            const __nv_bfloat16* Wp = g_Wih_bf + g1 * DD + kt * 16 + kc;
            a[mt][kt][0] = *(const u32*)(Wp);
            a[mt][kt][1] = *(const u32*)(Wp + 8 * DD);
            a[mt][kt][2] = *(const u32*)(Wp + 8);
            a[mt][kt][3] = *(const u32*)(Wp + 8 * DD + 8);
        }
    }
    float bs[4][2];
#pragma unroll
    for (int mt = 0; mt < 4; mt++) {
        bs[mt][0] = g_bias[mt * 128 + w * 16 + (lane >> 2)];
        bs[mt][1] = g_bias[mt * 128 + w * 16 + (lane >> 2) + 8];
    }
    __syncthreads();

    u32 xb = smem_u32(sX);
    const int jb = w * 16 + (lane >> 2);
    const int n0 = (lane & 3) * 2;

    for (int nt = 0; nt < 16; nt++) {
        u32 bf[8][2];
#pragma unroll
        for (int kt = 0; kt < 8; kt++)
            ldsm_x2t(bf[kt], xb + (kt * 16 + (lane & 15)) * XPITCH + nt * 16);
        float acc[4][4];
#pragma unroll
        for (int mt = 0; mt < 4; mt++) {
            acc[mt][0] = acc[mt][1] = acc[mt][2] = acc[mt][3] = 0.f;
#pragma unroll
            for (int kt = 0; kt < 8; kt++) mma16816(acc[mt], a[mt][kt], bf[kt]);
        }
#pragma unroll
        for (int e = 0; e < 4; e++) {
            int j = jb + (e >> 1) * 8;
            int tok = tokbase + nt * 8 + n0 + (e & 1);
            __nv_bfloat162 p0 = __floats2bfloat162_rn(acc[0][e] + bs[0][e >> 1],
                                                      acc[1][e] + bs[1][e >> 1]);
            __nv_bfloat162 p1 = __floats2bfloat162_rn(acc[2][e] + bs[2][e >> 1],
                                                      acc[3][e] + bs[3][e >> 1]);
            uint2 v = make_uint2(*(u32*)&p0, *(u32*)&p1);
            *(uint2*)(g_xg + (size_t)tok * G4 + j * 4) = v;
        }
    }
}

// ---------------- recurrent kernel: 4-slot xg ring, unroll-4 time loop ----------------
__global__ void __launch_bounds__(256, 1)
lstm_rec(const int* __restrict__ tokens, const int* __restrict__ lengths,
         const float* __restrict__ onehot, const float* __restrict__ h0,
         const float* __restrict__ c0, const float* __restrict__ linW,
         const float* __restrict__ linb, float* __restrict__ out) {
    __shared__ __align__(16) unsigned char hb[2][HH * 16];  // double-buffered h tile [k][s] bf16
    __shared__ int stok[BC * SS];
    __shared__ float shl[BC * HH];

    const int tid = threadIdx.x;
    const int w = tid >> 5, lane = tid & 31;
    const int base_s = blockIdx.x * BC;

    for (int i = tid; i < BC * SS; i += 256) {
        int s = i >> 9, t = i & 511;
        stok[s * SS + t] = tokens[(size_t)(base_s + s) * SS + t];
    }
    for (int i = tid; i < HH * BC; i += 256) {
        int j = i >> 3, s = i & 7;
        *(__nv_bfloat16*)(hb[0] + j * 16 + s * 2) = __float2bfloat16(h0[j]);
    }
    // CRITICAL: stok/hb[0] are read cross-thread below — must complete staging first.
    // (The missing barrier here was the timing-dependent illegal-access in R12/R14.)
    __syncthreads();

    // A fragments (W_hh) register-resident for all 512 steps
    u32 a[4][8][4];
#pragma unroll
    for (int mt = 0; mt < 4; mt++) {
        int g1 = mt * 128 + w * 16 + (lane >> 2);
        int kc = (lane & 3) * 2;
#pragma unroll
        for (int kt = 0; kt < 8; kt++) {
            const __nv_bfloat16* Wp = g_Whh_bf + g1 * HH + kt * 16 + kc;
            a[mt][kt][0] = *(const u32*)(Wp);
            a[mt][kt][1] = *(const u32*)(Wp + 8 * HH);
            a[mt][kt][2] = *(const u32*)(Wp + 8);
            a[mt][kt][3] = *(const u32*)(Wp + 8 * HH + 8);
        }
    }

    const int jb = w * 16 + (lane >> 2);
    const int s0 = (lane & 3) * 2;
    u32 hbase0 = smem_u32(hb[0]);
    u32 hbase1 = smem_u32(hb[1]);

    float c[4], hl[4];
    int len_[2];
    len_[0] = lengths[base_s + s0];
    len_[1] = lengths[base_s + s0 + 1];
#pragma unroll
    for (int e = 0; e < 4; e++) {
        c[e] = c0[jb + (e >> 1) * 8];
        hl[e] = 0.f;
    }

    // 4-slot xg ring: slot u holds data for the next step with (t % 4) == u.
    // Reloaded 4 steps ahead right after consumption -> no cross-iteration copies.
    u64 xq[4][4];
#pragma unroll
    for (int slot = 0; slot < 4; slot++)
#pragma unroll
        for (int e = 0; e < 4; e++) {
            int tok = stok[(s0 + (e & 1)) * SS + slot];
            xq[slot][e] = *(const u64*)(g_xg + (size_t)tok * G4 + (jb + (e >> 1) * 8) * 4);
        }

    int p = 0;
    for (int tb = 0; tb < SS; tb += 4) {
#pragma unroll
        for (int u = 0; u < 4; u++) {
            const int t = tb + u;

            // take this slot's (long-completed) data to locals, then re-issue for t+4
            u64 xc[4];
#pragma unroll
            for (int e = 0; e < 4; e++) xc[e] = xq[u][e];
            if (t + 4 < SS) {
#pragma unroll
                for (int e = 0; e < 4; e++) {
                    int tok = stok[(s0 + (e & 1)) * SS + t + 4];
                    xq[u][e] = *(const u64*)(g_xg + (size_t)tok * G4 + (jb + (e >> 1) * 8) * 4);
                }
            }

            u32 hrd = p ? hbase1 : hbase0;
            unsigned char* hwr = hb[p ^ 1];

            u32 bf[8][2];
#pragma unroll
            for (int kt = 0; kt < 8; kt++)
                ldsm_x2t(bf[kt], hrd + (kt * 16 + (lane & 15)) * 16);

            float acc[4][4];
#pragma unroll
            for (int mt = 0; mt < 4; mt++) {
                acc[mt][0] = acc[mt][1] = acc[mt][2] = acc[mt][3] = 0.f;
#pragma unroll
                for (int kt = 0; kt < 8; kt++) mma16816(acc[mt], a[mt][kt], bf[kt]);
            }

            float hv[4];
#pragma unroll
            for (int e = 0; e < 4; e++) {
                u32 lo = (u32)xc[e], hi = (u32)(xc[e] >> 32);
                float pi = acc[0][e] + bf_lo(lo);
                float pf = acc[1][e] + bf_hi(lo);
                float pg = acc[2][e] + bf_lo(hi);
                float po = acc[3][e] + bf_hi(hi);
                float iv = sig_ap(pi), fv = sig_ap(pf), ov = sig_ap(po);
                float gv = tanh_ap(pg);
                c[e] = fmaf(fv, c[e], iv * gv);
                hv[e] = ov * tanh_ap(c[e]);  // fast path feeds recurrence
                if (t == len_[e & 1] - 1) hl[e] = fmaxf(ov * tanh_acc(c[e]), 0.f);
            }
            // combined u32 stores: (jb, s0/s0+1) and (jb+8, s0/s0+1)
            {
                __nv_bfloat162 pa = __floats2bfloat162_rn(hv[0], hv[1]);
                *(u32*)(hwr + jb * 16 + s0 * 2) = *(u32*)&pa;
                __nv_bfloat162 pb = __floats2bfloat162_rn(hv[2], hv[3]);
                *(u32*)(hwr + (jb + 8) * 16 + s0 * 2) = *(u32*)&pb;
            }
            __syncthreads();  // h(t+1) tile visible; releases read buffer
            p ^= 1;
        }
    }

#pragma unroll
    for (int e = 0; e < 4; e++)
        shl[(s0 + (e & 1)) * HH + jb + (e >> 1) * 8] = hl[e];
    __syncthreads();
    if (tid < BC * 2) {
        int s = tid >> 1, m = tid & 1;
        const float* wrow = linW + m * (HH + NOPS);
        float acc = linb[m];
#pragma unroll 8
        for (int jj = 0; jj < HH; jj++) acc = fmaf(shl[s * HH + jj], wrow[jj], acc);
#pragma unroll
        for (int pp = 0; pp < NOPS; pp++)
            acc = fmaf(onehot[(base_s + s) * NOPS + pp], wrow[HH + pp], acc);
        out[(base_s + s) * 2 + m] = acc;
    }
}

// ---------------- launch ----------------
extern "C" void kernel_launch(void* const* d_in, const int* in_sizes, int n_in,
                              void* d_out, int out_size) {
    const int* tokens = (const int*)d_in[0];
    const int* lengths = (const int*)d_in[1];
    const float* onehot = (const float*)d_in[2];
    const float* emb = (const float*)d_in[3];
    const float* Wih = (const float*)d_in[4];
    const float* Whh = (const float*)d_in[5];
    const float* bih = (const float*)d_in[6];
    const float* bhh = (const float*)d_in[7];
    const float* h0 = (const float*)d_in[8];
    const float* c0 = (const float*)d_in[9];
    const float* linW = (const float*)d_in[10];
    const float* linb = (const float*)d_in[11];
    float* out = (float*)d_out;

    setup_kernel<<<512, 256>>>(Wih, Whh, bih, bhh);
    phaseA_kernel<<<VSZ / 128, 256>>>(emb);
    lstm_rec<<<NCTA, 256>>>(tokens, lengths, onehot, h0, c0, linW, linb, out);
}

// round 16
// speedup vs baseline: 1.3830x; 1.0058x over previous
#include <cuda_runtime.h>
#include <cuda_bf16.h>
#include <cstdint>

#define SS   512
#define G4   512
#define HH   128
#define DD   128
#define VSZ  64000
#define BC   8
#define NCTA 128
#define NOPS 16

typedef unsigned int u32;
typedef unsigned long long u64;

// ---------------- device globals ----------------
// xg[token][j*4 + type] bf16: x-path precomputed with bias (i,f,g,o per j)
__device__ __align__(16) __nv_bfloat16 g_xg[(size_t)VSZ * G4];  // 64 MB

// ---------------- helpers ----------------
__device__ __forceinline__ u32 smem_u32(const void* p) {
    u32 a;
    asm("{ .reg .u64 t; cvta.to.shared.u64 t, %1; cvt.u32.u64 %0, t; }" : "=r"(a) : "l"(p));
    return a;
}
__device__ __forceinline__ void mma16816(float* d, const u32* a, const u32* b) {
    asm volatile(
        "mma.sync.aligned.m16n8k16.row.col.f32.bf16.bf16.f32 "
        "{%0,%1,%2,%3},{%4,%5,%6,%7},{%8,%9},{%0,%1,%2,%3};"
        : "+f"(d[0]), "+f"(d[1]), "+f"(d[2]), "+f"(d[3])
        : "r"(a[0]), "r"(a[1]), "r"(a[2]), "r"(a[3]), "r"(b[0]), "r"(b[1]));
}
__device__ __forceinline__ void ldsm_x2t(u32* r, u32 addr) {
    asm volatile("ldmatrix.sync.aligned.m8n8.x2.trans.shared.b16 {%0,%1},[%2];"
                 : "=r"(r[0]), "=r"(r[1]) : "r"(addr));
}
__device__ __forceinline__ float ex2_ap(float x) {
    float y; asm("ex2.approx.f32 %0, %1;" : "=f"(y) : "f"(x)); return y;
}
__device__ __forceinline__ float rcp_ap(float x) {
    float y; asm("rcp.approx.f32 %0, %1;" : "=f"(y) : "f"(x)); return y;
}
__device__ __forceinline__ float tanh_ap(float x) {
    float y; asm("tanh.approx.f32 %0, %1;" : "=f"(y) : "f"(x)); return y;
}
__device__ __forceinline__ float sig_ap(float x) {
    return fmaf(tanh_ap(x * 0.5f), 0.5f, 0.5f);
}
// accurate tanh (output-path h_last capture only)
__device__ __forceinline__ float tanh_acc(float x) {
    return 1.f - 2.f * rcp_ap(1.f + ex2_ap(2.885390081777927f * x));
}
__device__ __forceinline__ float bf_lo(u32 p) { return __uint_as_float(p << 16); }
__device__ __forceinline__ float bf_hi(u32 p) { return __uint_as_float(p & 0xFFFF0000u); }
__device__ __forceinline__ u32 pack_bf2(float lo, float hi) {
    __nv_bfloat162 p = __floats2bfloat162_rn(lo, hi);
    return *(u32*)&p;
}

// ---------------- Phase A: xg = W_ih @ relu(emb) + bias, all tokens ----------------
#define XPITCH 272
__global__ void __launch_bounds__(256, 1)
phaseA_kernel(const float* __restrict__ emb, const float* __restrict__ Wih,
              const float* __restrict__ bih, const float* __restrict__ bhh) {
    __shared__ __align__(16) unsigned char sX[128 * XPITCH];
    const int tid = threadIdx.x;
    const int w = tid >> 5, lane = tid & 31;
    const int tokbase = blockIdx.x * 128;

    {
        int r = tid >> 1, half = tid & 1;
        const float* er = emb + (size_t)(tokbase + r) * DD + half * 64;
#pragma unroll 4
        for (int cc = 0; cc < 64; cc += 4) {
            float4 f = *(const float4*)(er + cc);
            int d0 = half * 64 + cc;
            *(__nv_bfloat16*)(sX + (d0 + 0) * XPITCH + r * 2) = __float2bfloat16(fmaxf(f.x, 0.f));
            *(__nv_bfloat16*)(sX + (d0 + 1) * XPITCH + r * 2) = __float2bfloat16(fmaxf(f.y, 0.f));
            *(__nv_bfloat16*)(sX + (d0 + 2) * XPITCH + r * 2) = __float2bfloat16(fmaxf(f.z, 0.f));
            *(__nv_bfloat16*)(sX + (d0 + 3) * XPITCH + r * 2) = __float2bfloat16(fmaxf(f.w, 0.f));
        }
    }

    // A fragments (W_ih) converted fp32 -> bf16 in-flight
    u32 a[4][8][4];
#pragma unroll
    for (int mt = 0; mt < 4; mt++) {
        int g1 = mt * 128 + w * 16 + (lane >> 2);
        int kc = (lane & 3) * 2;
#pragma unroll
        for (int kt = 0; kt < 8; kt++) {
            const float* Wp = Wih + g1 * DD + kt * 16 + kc;
            float2 f0 = *(const float2*)(Wp);
            float2 f1 = *(const float2*)(Wp + 8 * DD);
            float2 f2 = *(const float2*)(Wp + 8);
            float2 f3 = *(const float2*)(Wp + 8 * DD + 8);
            a[mt][kt][0] = pack_bf2(f0.x, f0.y);
            a[mt][kt][1] = pack_bf2(f1.x, f1.y);
            a[mt][kt][2] = pack_bf2(f2.x, f2.y);
            a[mt][kt][3] = pack_bf2(f3.x, f3.y);
        }
    }
    float bs[4][2];
#pragma unroll
    for (int mt = 0; mt < 4; mt++) {
        int g1 = mt * 128 + w * 16 + (lane >> 2);
        bs[mt][0] = bih[g1] + bhh[g1];
        bs[mt][1] = bih[g1 + 8] + bhh[g1 + 8];
    }
    __syncthreads();

    u32 xb = smem_u32(sX);
    const int jb = w * 16 + (lane >> 2);
    const int n0 = (lane & 3) * 2;

    for (int nt = 0; nt < 16; nt++) {
        u32 bf[8][2];
#pragma unroll
        for (int kt = 0; kt < 8; kt++)
            ldsm_x2t(bf[kt], xb + (kt * 16 + (lane & 15)) * XPITCH + nt * 16);
        float acc[4][4];
#pragma unroll
        for (int mt = 0; mt < 4; mt++) {
            acc[mt][0] = acc[mt][1] = acc[mt][2] = acc[mt][3] = 0.f;
#pragma unroll
            for (int kt = 0; kt < 8; kt++) mma16816(acc[mt], a[mt][kt], bf[kt]);
        }
#pragma unroll
        for (int e = 0; e < 4; e++) {
            int j = jb + (e >> 1) * 8;
            int tok = tokbase + nt * 8 + n0 + (e & 1);
            uint2 v = make_uint2(
                pack_bf2(acc[0][e] + bs[0][e >> 1], acc[1][e] + bs[1][e >> 1]),
                pack_bf2(acc[2][e] + bs[2][e >> 1], acc[3][e] + bs[3][e >> 1]));
            *(uint2*)(g_xg + (size_t)tok * G4 + j * 4) = v;
        }
    }
}

// ---------------- recurrent kernel: 4-slot xg ring, unroll-4 time loop ----------------
__global__ void __launch_bounds__(256, 1)
lstm_rec(const int* __restrict__ tokens, const int* __restrict__ lengths,
         const float* __restrict__ onehot, const float* __restrict__ Whh,
         const float* __restrict__ h0, const float* __restrict__ c0,
         const float* __restrict__ linW, const float* __restrict__ linb,
         float* __restrict__ out) {
    __shared__ __align__(16) unsigned char hb[2][HH * 16];  // double-buffered h tile [k][s] bf16
    __shared__ int stok[BC * SS];
    __shared__ float shl[BC * HH];

    const int tid = threadIdx.x;
    const int w = tid >> 5, lane = tid & 31;
    const int base_s = blockIdx.x * BC;

    for (int i = tid; i < BC * SS; i += 256) {
        int s = i >> 9, t = i & 511;
        stok[s * SS + t] = tokens[(size_t)(base_s + s) * SS + t];
    }
    for (int i = tid; i < HH * BC; i += 256) {
        int j = i >> 3, s = i & 7;
        *(__nv_bfloat16*)(hb[0] + j * 16 + s * 2) = __float2bfloat16(h0[j]);
    }
    // stok/hb[0] are read cross-thread below — staging must complete first.
    __syncthreads();

    // A fragments (W_hh) converted fp32 -> bf16 in-flight; register-resident for all steps
    u32 a[4][8][4];
#pragma unroll
    for (int mt = 0; mt < 4; mt++) {
        int g1 = mt * 128 + w * 16 + (lane >> 2);
        int kc = (lane & 3) * 2;
#pragma unroll
        for (int kt = 0; kt < 8; kt++) {
            const float* Wp = Whh + g1 * HH + kt * 16 + kc;
            float2 f0 = *(const float2*)(Wp);
            float2 f1 = *(const float2*)(Wp + 8 * HH);
            float2 f2 = *(const float2*)(Wp + 8);
            float2 f3 = *(const float2*)(Wp + 8 * HH + 8);
            a[mt][kt][0] = pack_bf2(f0.x, f0.y);
            a[mt][kt][1] = pack_bf2(f1.x, f1.y);
            a[mt][kt][2] = pack_bf2(f2.x, f2.y);
            a[mt][kt][3] = pack_bf2(f3.x, f3.y);
        }
    }

    const int jb = w * 16 + (lane >> 2);
    const int s0 = (lane & 3) * 2;
    u32 hbase0 = smem_u32(hb[0]);
    u32 hbase1 = smem_u32(hb[1]);

    float c[4], hl[4];
    int len_[2];
    len_[0] = lengths[base_s + s0];
    len_[1] = lengths[base_s + s0 + 1];
#pragma unroll
    for (int e = 0; e < 4; e++) {
        c[e] = c0[jb + (e >> 1) * 8];
        hl[e] = 0.f;
    }

    // 4-slot xg ring: slot u holds data for the next step with (t % 4) == u.
    u64 xq[4][4];
#pragma unroll
    for (int slot = 0; slot < 4; slot++)
#pragma unroll
        for (int e = 0; e < 4; e++) {
            int tok = stok[(s0 + (e & 1)) * SS + slot];
            xq[slot][e] = *(const u64*)(g_xg + (size_t)tok * G4 + (jb + (e >> 1) * 8) * 4);
        }

    int p = 0;
    for (int tb = 0; tb < SS; tb += 4) {
#pragma unroll
        for (int u = 0; u < 4; u++) {
            const int t = tb + u;

            u64 xc[4];
#pragma unroll
            for (int e = 0; e < 4; e++) xc[e] = xq[u][e];
            if (t + 4 < SS) {
#pragma unroll
                for (int e = 0; e < 4; e++) {
                    int tok = stok[(s0 + (e & 1)) * SS + t + 4];
                    xq[u][e] = *(const u64*)(g_xg + (size_t)tok * G4 + (jb + (e >> 1) * 8) * 4);
                }
            }

            u32 hrd = p ? hbase1 : hbase0;
            unsigned char* hwr = hb[p ^ 1];

            u32 bf[8][2];
#pragma unroll
            for (int kt = 0; kt < 8; kt++)
                ldsm_x2t(bf[kt], hrd + (kt * 16 + (lane & 15)) * 16);

            // issue g/o tiles first, i/f last: post-HMMA activation chain starts
            // from early accumulators (tanh(g), sig(o) overlap the late HMMAs)
            float acc[4][4];
            const int mord[4] = {2, 3, 0, 1};
#pragma unroll
            for (int mi = 0; mi < 4; mi++) {
                int mt = mord[mi];
                acc[mt][0] = acc[mt][1] = acc[mt][2] = acc[mt][3] = 0.f;
#pragma unroll
                for (int kt = 0; kt < 8; kt++) mma16816(acc[mt], a[mt][kt], bf[kt]);
            }

            float hv[4], ovv[4];
#pragma unroll
            for (int e = 0; e < 4; e++) {
                u32 lo = (u32)xc[e], hi = (u32)(xc[e] >> 32);
                float gv = tanh_ap(acc[2][e] + bf_lo(hi));
                float ov = sig_ap(acc[3][e] + bf_hi(hi));
                float iv = sig_ap(acc[0][e] + bf_lo(lo));
                float fv = sig_ap(acc[1][e] + bf_hi(lo));
                c[e] = fmaf(fv, c[e], iv * gv);
                hv[e] = ov * tanh_ap(c[e]);
                ovv[e] = ov;
            }
            // combined u32 stores: (jb, s0/s0+1) and (jb+8, s0/s0+1)
            *(u32*)(hwr + jb * 16 + s0 * 2) = pack_bf2(hv[0], hv[1]);
            *(u32*)(hwr + (jb + 8) * 16 + s0 * 2) = pack_bf2(hv[2], hv[3]);

            // rare accurate capture of h_last (branch taken ~8/512 steps per warp)
            if (t == len_[0] - 1 || t == len_[1] - 1) {
#pragma unroll
                for (int e = 0; e < 4; e++)
                    if (t == len_[e & 1] - 1)
                        hl[e] = fmaxf(ovv[e] * tanh_acc(c[e]), 0.f);
            }
            __syncthreads();  // h(t+1) tile visible; releases read buffer
            p ^= 1;
        }
    }

#pragma unroll
    for (int e = 0; e < 4; e++)
        shl[(s0 + (e & 1)) * HH + jb + (e >> 1) * 8] = hl[e];
    __syncthreads();
    if (tid < BC * 2) {
        int s = tid >> 1, m = tid & 1;
        const float* wrow = linW + m * (HH + NOPS);
        float acc = linb[m];
#pragma unroll 8
        for (int jj = 0; jj < HH; jj++) acc = fmaf(shl[s * HH + jj], wrow[jj], acc);
#pragma unroll
        for (int pp = 0; pp < NOPS; pp++)
            acc = fmaf(onehot[(base_s + s) * NOPS + pp], wrow[HH + pp], acc);
        out[(base_s + s) * 2 + m] = acc;
    }
}

// ---------------- launch ----------------
extern "C" void kernel_launch(void* const* d_in, const int* in_sizes, int n_in,
                              void* d_out, int out_size) {
    const int* tokens = (const int*)d_in[0];
    const int* lengths = (const int*)d_in[1];
    const float* onehot = (const float*)d_in[2];
    const float* emb = (const float*)d_in[3];
    const float* Wih = (const float*)d_in[4];
    const float* Whh = (const float*)d_in[5];
    const float* bih = (const float*)d_in[6];
    const float* bhh = (const float*)d_in[7];
    const float* h0 = (const float*)d_in[8];
    const float* c0 = (const float*)d_in[9];
    const float* linW = (const float*)d_in[10];
    const float* linb = (const float*)d_in[11];
    float* out = (float*)d_out;

    phaseA_kernel<<<VSZ / 128, 256>>>(emb, Wih, bih, bhh);
    lstm_rec<<<NCTA, 256>>>(tokens, lengths, onehot, Whh, h0, c0, linW, linb, out);
}